// round 8
// baseline (speedup 1.0000x reference)
#include <cuda_runtime.h>
#include <cuda_bf16.h>
#include <cstdint>

#define BATCH 4
#define CH    64
#define NPTS  4096
#define KNN   32
#define NOUT  64

// ---------------- device scratch (static: no allocations allowed) ----------------
__device__ float          g_sq   [BATCH*NPTS];
__device__ int            g_idx  [BATCH*NPTS*KNN];
__device__ float          g_Y1   [BATCH*NPTS*NOUT];
__device__ float          g_Y2   [BATCH*NPTS*NOUT];
__device__ float          g_hmax [BATCH*NPTS*NOUT];
__device__ float          g_hmin [BATCH*NPTS*NOUT];
__device__ float          g_Wt1  [CH*NOUT];
__device__ float          g_Wt2  [CH*NOUT];
__device__ float          g_sum  [NOUT];
__device__ float          g_sumsq[NOUT];
__device__ float          g_a    [NOUT];
__device__ float          g_c    [NOUT];
__device__ unsigned short g_Xhi  [BATCH*NPTS*CH];   // bf16 hi, (n, c) row-major
__device__ unsigned short g_Xlo  [BATCH*NPTS*CH];   // bf16 lo

// ---------------- helpers ----------------
__device__ __forceinline__ uint32_t smem_u32(const void* p){
    uint32_t a;
    asm("{ .reg .u64 t; cvta.to.shared.u64 t, %1; cvt.u32.u64 %0, t; }" : "=r"(a) : "l"(p));
    return a;
}
__device__ __forceinline__ void ldsm_x4(uint32_t& r0, uint32_t& r1, uint32_t& r2, uint32_t& r3,
                                        uint32_t addr){
    asm volatile("ldmatrix.sync.aligned.m8n8.x4.shared.b16 {%0,%1,%2,%3}, [%4];"
                 : "=r"(r0), "=r"(r1), "=r"(r2), "=r"(r3) : "r"(addr));
}
__device__ __forceinline__ void mma_bf16(float* d, const uint32_t* a, uint32_t b0, uint32_t b1){
    asm volatile("mma.sync.aligned.m16n8k16.row.col.f32.bf16.bf16.f32 "
                 "{%0,%1,%2,%3}, {%4,%5,%6,%7}, {%8,%9}, {%0,%1,%2,%3};"
                 : "+f"(d[0]), "+f"(d[1]), "+f"(d[2]), "+f"(d[3])
                 : "r"(a[0]), "r"(a[1]), "r"(a[2]), "r"(a[3]), "r"(b0), "r"(b1));
}

// ---------------- kernel 0a: Wt1 = (W1-W2)^T, Wt2 = W2^T ----------------
__global__ void wprep_kernel(const float* __restrict__ W){
    int t = blockIdx.x*256 + threadIdx.x;
    if (t < CH*NOUT){
        int o = t & 63, c = t >> 6;
        float w1 = W[o*2*CH + c];
        float w2 = W[o*2*CH + CH + c];
        g_Wt1[c*NOUT + o] = w1 - w2;
        g_Wt2[c*NOUT + o] = w2;
    }
}

// ---------------- kernel 0b: squared norms ----------------
__global__ void sqnorm_kernel(const float* __restrict__ points){
    int t = blockIdx.x*256 + threadIdx.x;
    int b = t >> 12, n = t & (NPTS-1);
    const float* P = points + b*CH*NPTS + n;
    float s = 0.f;
    #pragma unroll
    for (int c = 0; c < CH; ++c){ float v = __ldg(P + c*NPTS); s = fmaf(v, v, s); }
    g_sq[t] = s;
}

// ---------------- kernel 0c: zero BN accumulators ----------------
__global__ void zero_kernel(){
    int t = threadIdx.x;
    if (t < NOUT){ g_sum[t] = 0.f; g_sumsq[t] = 0.f; }
}

// ---------------- kernel 0d: transpose + bf16 hi/lo split ----------------
__global__ void __launch_bounds__(256) prep_bf16_kernel(const float* __restrict__ points){
    __shared__ unsigned short his[64][66];
    __shared__ unsigned short los[64][66];
    const int tid = threadIdx.x;
    const int bn0 = blockIdx.x * 64;
    const int b = bn0 >> 12;
    const int n0 = bn0 & (NPTS-1);
    const int nl = tid & 63;
    const int cg = tid >> 6;

    #pragma unroll
    for (int i = 0; i < 16; ++i){
        int c = cg*16 + i;
        float x = __ldg(points + b*CH*NPTS + c*NPTS + n0 + nl);
        __nv_bfloat16 h = __float2bfloat16(x);
        __nv_bfloat16 l = __float2bfloat16(x - __bfloat162float(h));
        his[nl][c] = __bfloat16_as_ushort(h);
        los[nl][c] = __bfloat16_as_ushort(l);
    }
    __syncthreads();

    #pragma unroll
    for (int it = 0; it < 2; ++it){
        int idx = it*256 + tid;
        int row = idx >> 3, c16 = idx & 7;
        uint32_t w[4];
        #pragma unroll
        for (int p = 0; p < 4; ++p)
            w[p] = (uint32_t)his[row][c16*8 + 2*p] | ((uint32_t)his[row][c16*8 + 2*p + 1] << 16);
        *reinterpret_cast<uint4*>(g_Xhi + (bn0+row)*CH + c16*8) = make_uint4(w[0],w[1],w[2],w[3]);
        #pragma unroll
        for (int p = 0; p < 4; ++p)
            w[p] = (uint32_t)los[row][c16*8 + 2*p] | ((uint32_t)los[row][c16*8 + 2*p + 1] << 16);
        *reinterpret_cast<uint4*>(g_Xlo + (bn0+row)*CH + c16*8) = make_uint4(w[0],w[1],w[2],w[3]);
    }
}

// ---------------- kernel 1: HMMA distance GEMM + register top-32 ----------------
// grid = BATCH*32 blocks x 512 threads (16 warps, 4x4 warp grid, 32q x 32m tiles).
// Block owns 128 queries; streams 4096 candidates in chunks of 128.
// dot = hi*hi + hi*lo + lo*hi via mma.sync m16n8k16 bf16 (baseline PTX, tensor pipe).
// Score = sq_m - 2*dot, selection = R6 ballot/shfl sorted-list (exact).
// smem (bytes): Ahi 18432 | Alo 18432 | Bhi 18432 | Blo 18432 | Sc 128*130*4 | Ss 16384
#define PITCHB  144          // 72 bf16 per row: conflict-free ldmatrix
#define AHI_OFF 0
#define ALO_OFF 18432
#define BHI_OFF 36864
#define BLO_OFF 55296
#define SC_OFF  73728
#define SS_OFF  (SC_OFF + 128*130*4)
#define KNN_SMEM (SS_OFF + 4096*4)

__global__ void __launch_bounds__(512, 1) knn_kernel(){
    extern __shared__ char sm[];
    const uint32_t smb = smem_u32(sm);
    float* Sc = reinterpret_cast<float*>(sm + SC_OFF);
    float* Ss = reinterpret_cast<float*>(sm + SS_OFF);

    const int tid  = threadIdx.x;
    const int lane = tid & 31;
    const int wid  = tid >> 5;
    const int wq   = wid >> 2;          // warp row (query group of 32)
    const int wm   = wid & 3;           // warp col (candidate group of 32)
    const int b     = blockIdx.x >> 5;
    const int qbase = (blockIdx.x & 31) * 128;

    // ---- load A tiles (128 q x 64 ch, hi+lo), 144B pitch ----
    {
        const uint4* srcH = reinterpret_cast<const uint4*>(g_Xhi + (b*NPTS + qbase)*CH);
        const uint4* srcL = reinterpret_cast<const uint4*>(g_Xlo + (b*NPTS + qbase)*CH);
        #pragma unroll
        for (int it = 0; it < 2; ++it){
            int idx = it*512 + tid;            // 0..1023 = row*8 + seg
            int off = (idx >> 3)*PITCHB + (idx & 7)*16;
            *reinterpret_cast<uint4*>(sm + AHI_OFF + off) = __ldg(srcH + idx);
            *reinterpret_cast<uint4*>(sm + ALO_OFF + off) = __ldg(srcL + idx);
        }
        #pragma unroll
        for (int it = 0; it < 2; ++it){
            int idx = it*512 + tid;
            reinterpret_cast<float4*>(Ss)[idx] =
                __ldg(reinterpret_cast<const float4*>(g_sq + b*NPTS) + idx);
        }
    }

    // ldmatrix lane offset within a 16-row x 16-col bf16 tile
    const uint32_t lm_off = (uint32_t)((lane & 15)*PITCHB + (lane >> 4)*16);
    const uint32_t aRow = smb + (uint32_t)(wq*32*PITCHB) + lm_off;   // + term_off + ks*32 (+16 rows)
    const uint32_t bRow = smb + (uint32_t)(wm*32*PITCHB) + lm_off;

    // per-(warp,query) sorted top-32: lane l holds l-th smallest (warp owns q 8*wid..+7)
    float Lv[8]; int Li[8]; float thr[8];
    #pragma unroll
    for (int qi = 0; qi < 8; ++qi){ Lv[qi] = 3.0e38f; Li[qi] = 0; thr[qi] = 3.0e38f; }

    #pragma unroll 1
    for (int chunk = 0; chunk < NPTS/128; ++chunk){
        const int mbase = chunk * 128;

        // ---- fill B tiles (hi+lo) ----
        {
            const uint4* srcH = reinterpret_cast<const uint4*>(g_Xhi + (b*NPTS + mbase)*CH);
            const uint4* srcL = reinterpret_cast<const uint4*>(g_Xlo + (b*NPTS + mbase)*CH);
            #pragma unroll
            for (int it = 0; it < 2; ++it){
                int idx = it*512 + tid;
                int off = (idx >> 3)*PITCHB + (idx & 7)*16;
                *reinterpret_cast<uint4*>(sm + BHI_OFF + off) = __ldg(srcH + idx);
                *reinterpret_cast<uint4*>(sm + BLO_OFF + off) = __ldg(srcL + idx);
            }
        }
        __syncthreads();     // B ready; also gates next-chunk B overwrite vs prior compute

        // ---- 32q x 32m tile via 12 k-steps of m16n8k16 ----
        float acc[8][4];
        #pragma unroll
        for (int f = 0; f < 8; ++f)
            #pragma unroll
            for (int e = 0; e < 4; ++e) acc[f][e] = 0.f;

        #pragma unroll 1
        for (int term = 0; term < 3; ++term){
            const uint32_t aOff = (term == 2) ? ALO_OFF : AHI_OFF;
            const uint32_t bOff = (term == 1) ? BLO_OFF : BHI_OFF;
            #pragma unroll
            for (int ks = 0; ks < 4; ++ks){
                uint32_t a0[4], a1[4];
                ldsm_x4(a0[0],a0[1],a0[2],a0[3], aRow + aOff + ks*32);
                ldsm_x4(a1[0],a1[1],a1[2],a1[3], aRow + aOff + ks*32 + 16*PITCHB);
                uint32_t p0,p1,p2,p3, q0,q1,q2,q3;
                ldsm_x4(p0,p1,p2,p3, bRow + bOff + ks*32);               // n 0-15
                ldsm_x4(q0,q1,q2,q3, bRow + bOff + ks*32 + 16*PITCHB);   // n 16-31
                // b-frags: {p0,p2}=n0-7, {p1,p3}=n8-15, {q0,q2}=n16-23, {q1,q3}=n24-31
                mma_bf16(acc[0], a0, p0, p2);
                mma_bf16(acc[1], a0, p1, p3);
                mma_bf16(acc[2], a0, q0, q2);
                mma_bf16(acc[3], a0, q1, q3);
                mma_bf16(acc[4], a1, p0, p2);
                mma_bf16(acc[5], a1, p1, p3);
                mma_bf16(acc[6], a1, q0, q2);
                mma_bf16(acc[7], a1, q1, q3);
            }
        }

        // ---- store d-frags to Sc[q][m] (stride 130, float2-aligned) ----
        {
            int r = lane >> 2, c2 = (lane & 3)*2;
            float* base = Sc + (wq*32 + r)*130 + wm*32 + c2;
            #pragma unroll
            for (int rg = 0; rg < 2; ++rg)
                #pragma unroll
                for (int cg = 0; cg < 4; ++cg){
                    float* p = base + rg*16*130 + cg*8;
                    *reinterpret_cast<float2*>(p)         = make_float2(acc[rg*4+cg][0], acc[rg*4+cg][1]);
                    *reinterpret_cast<float2*>(p + 8*130) = make_float2(acc[rg*4+cg][2], acc[rg*4+cg][3]);
                }
        }
        __syncthreads();     // Sc complete

        // ---- selection: warp owns queries 8*wid .. 8*wid+7 ----
        #pragma unroll 1
        for (int qi = 0; qi < 8; ++qi){
            const float* row = Sc + (8*wid + qi)*130;
            #pragma unroll 1
            for (int g = 0; g < 4; ++g){
                float dot = row[g*32 + lane];
                float sj = fmaf(-2.f, dot, Ss[mbase + g*32 + lane]);
                unsigned mask = __ballot_sync(0xffffffffu, sj < thr[qi]);
                while (mask){
                    int src = __ffs(mask) - 1;
                    mask &= mask - 1;
                    float v = __shfl_sync(0xffffffffu, sj, src);
                    int gi = mbase + g*32 + src;
                    int pos = __popc(__ballot_sync(0xffffffffu, Lv[qi] <= v));
                    float upv = __shfl_up_sync(0xffffffffu, Lv[qi], 1);
                    int   upi = __shfl_up_sync(0xffffffffu, Li[qi], 1);
                    if (lane == pos){ Lv[qi] = v; Li[qi] = gi; }
                    else if (lane > pos){ Lv[qi] = upv; Li[qi] = upi; }
                    thr[qi] = __shfl_sync(0xffffffffu, Lv[qi], 31);
                    mask &= __ballot_sync(0xffffffffu, sj < thr[qi]);
                }
            }
        }
        // no extra sync: selection reads only Sc; next B-fill races nothing
        // (everyone passed the post-store barrier before any new fill is visible? no ——
        //  fill writes B, compute that reads B is gated by the post-fill barrier, and
        //  every warp reaches that barrier only after finishing its selection.)
    }

    #pragma unroll
    for (int qi = 0; qi < 8; ++qi)
        g_idx[(b*NPTS + qbase + 8*wid + qi)*KNN + lane] = Li[qi];
}

// ---------------- kernel 2: Y1 = X*(W1-W2)^T, Y2 = X*W2^T ----------------
__global__ void __launch_bounds__(256, 1) ygemm_kernel(const float* __restrict__ points){
    extern __shared__ float smf[];
    float* Xs  = smf;           // [64][128]
    float* W1s = Xs + 64*128;   // [64][64]
    float* W2s = W1s + 64*64;   // [64][64]

    const int tid = threadIdx.x;
    const int b = blockIdx.x >> 5;
    const int nbase = (blockIdx.x & 31) * 128;
    const float* P = points + b*CH*NPTS;

    #pragma unroll
    for (int it = 0; it < 8; ++it){
        int idx = it*256 + tid;
        int c = idx >> 5, i4 = idx & 31;
        reinterpret_cast<float4*>(Xs + c*128)[i4] =
            __ldg(reinterpret_cast<const float4*>(P + c*NPTS + nbase) + i4);
    }
    #pragma unroll
    for (int it = 0; it < 4; ++it){
        int idx = it*256 + tid;
        reinterpret_cast<float4*>(W1s)[idx] = __ldg(reinterpret_cast<const float4*>(g_Wt1) + idx);
        reinterpret_cast<float4*>(W2s)[idx] = __ldg(reinterpret_cast<const float4*>(g_Wt2) + idx);
    }
    __syncthreads();

    const int n0 = (tid & 31) * 4;
    const int o0 = (tid >> 5) * 8;
    float acc1[4][8], acc2[4][8];
    #pragma unroll
    for (int j = 0; j < 4; ++j)
        #pragma unroll
        for (int r = 0; r < 8; ++r){ acc1[j][r] = 0.f; acc2[j][r] = 0.f; }

    #pragma unroll 8
    for (int c = 0; c < CH; ++c){
        float4 a   = *reinterpret_cast<const float4*>(Xs  + c*128 + n0);
        float4 w10 = *reinterpret_cast<const float4*>(W1s + c*64 + o0);
        float4 w11 = *reinterpret_cast<const float4*>(W1s + c*64 + o0 + 4);
        float4 w20 = *reinterpret_cast<const float4*>(W2s + c*64 + o0);
        float4 w21 = *reinterpret_cast<const float4*>(W2s + c*64 + o0 + 4);
        float af[4]  = {a.x, a.y, a.z, a.w};
        float w1f[8] = {w10.x,w10.y,w10.z,w10.w,w11.x,w11.y,w11.z,w11.w};
        float w2f[8] = {w20.x,w20.y,w20.z,w20.w,w21.x,w21.y,w21.z,w21.w};
        #pragma unroll
        for (int j = 0; j < 4; ++j)
            #pragma unroll
            for (int r = 0; r < 8; ++r){
                acc1[j][r] = fmaf(af[j], w1f[r], acc1[j][r]);
                acc2[j][r] = fmaf(af[j], w2f[r], acc2[j][r]);
            }
    }

    #pragma unroll
    for (int j = 0; j < 4; ++j){
        int row = (b*NPTS + nbase + n0 + j)*NOUT + o0;
        *reinterpret_cast<float4*>(g_Y1 + row)     = make_float4(acc1[j][0],acc1[j][1],acc1[j][2],acc1[j][3]);
        *reinterpret_cast<float4*>(g_Y1 + row + 4) = make_float4(acc1[j][4],acc1[j][5],acc1[j][6],acc1[j][7]);
        *reinterpret_cast<float4*>(g_Y2 + row)     = make_float4(acc2[j][0],acc2[j][1],acc2[j][2],acc2[j][3]);
        *reinterpret_cast<float4*>(g_Y2 + row + 4) = make_float4(acc2[j][4],acc2[j][5],acc2[j][6],acc2[j][7]);
    }
}

// ---------------- kernel 3: gather neighbors, h stats, per-(n,o) max/min over k ----------------
__global__ void __launch_bounds__(256, 1) gather_kernel(){
    __shared__ float ssum[NOUT], ssum2[NOUT];
    const int tid = threadIdx.x;
    if (tid < NOUT){ ssum[tid] = 0.f; ssum2[tid] = 0.f; }
    __syncthreads();

    const int b = blockIdx.x >> 6;
    const int nbase = (blockIdx.x & 63) * 64;
    const int lane = tid & 31, wid = tid >> 5;
    const int half = lane >> 4;
    const int c4 = lane & 15;

    const float4* Y1f = reinterpret_cast<const float4*>(g_Y1);
    const float4* Y2f = reinterpret_cast<const float4*>(g_Y2);
    float4* hmaxf = reinterpret_cast<float4*>(g_hmax);
    float4* hminf = reinterpret_cast<float4*>(g_hmin);

    float a0=0.f, a1=0.f, a2=0.f, a3=0.f;
    float b0=0.f, b1=0.f, b2=0.f, b3=0.f;

    #pragma unroll 1
    for (int it = 0; it < 4; ++it){
        int np  = nbase + it*16 + wid*2;
        int bnp = b*NPTS + np;
        int ia = g_idx[ bnp   *KNN + lane];
        int ib = g_idx[(bnp+1)*KNN + lane];
        int bn = bnp + half;
        float4 y1 = __ldg(Y1f + bn*16 + c4);
        float4 mx = make_float4(-3.0e38f,-3.0e38f,-3.0e38f,-3.0e38f);
        float4 mn = make_float4( 3.0e38f, 3.0e38f, 3.0e38f, 3.0e38f);
        #pragma unroll
        for (int k = 0; k < KNN; ++k){
            int ma = __shfl_sync(0xffffffffu, ia, k);
            int mb = __shfl_sync(0xffffffffu, ib, k);
            int m  = half ? mb : ma;
            float4 y2 = __ldg(Y2f + (b*NPTS + m)*16 + c4);
            float h0 = y1.x + y2.x, h1 = y1.y + y2.y, h2 = y1.z + y2.z, h3 = y1.w + y2.w;
            a0 += h0; a1 += h1; a2 += h2; a3 += h3;
            b0 = fmaf(h0,h0,b0); b1 = fmaf(h1,h1,b1); b2 = fmaf(h2,h2,b2); b3 = fmaf(h3,h3,b3);
            mx.x = fmaxf(mx.x,h0); mx.y = fmaxf(mx.y,h1); mx.z = fmaxf(mx.z,h2); mx.w = fmaxf(mx.w,h3);
            mn.x = fminf(mn.x,h0); mn.y = fminf(mn.y,h1); mn.z = fminf(mn.z,h2); mn.w = fminf(mn.w,h3);
        }
        hmaxf[bn*16 + c4] = mx;
        hminf[bn*16 + c4] = mn;
    }

    atomicAdd(&ssum [c4*4+0], a0); atomicAdd(&ssum [c4*4+1], a1);
    atomicAdd(&ssum [c4*4+2], a2); atomicAdd(&ssum [c4*4+3], a3);
    atomicAdd(&ssum2[c4*4+0], b0); atomicAdd(&ssum2[c4*4+1], b1);
    atomicAdd(&ssum2[c4*4+2], b2); atomicAdd(&ssum2[c4*4+3], b3);
    __syncthreads();
    if (tid < NOUT){
        atomicAdd(&g_sum[tid],   ssum[tid]);
        atomicAdd(&g_sumsq[tid], ssum2[tid]);
    }
}

// ---------------- kernel 4: BN scale/shift ----------------
__global__ void finalize_kernel(const float* __restrict__ gamma,
                                const float* __restrict__ beta){
    int o = threadIdx.x;
    if (o < NOUT){
        const float inv = 1.f / (float)(BATCH*NPTS*KNN);
        float mean = g_sum[o] * inv;
        float var  = g_sumsq[o] * inv - mean*mean;
        float a = gamma[o] * rsqrtf(var + 1e-5f);
        g_a[o] = a;
        g_c[o] = beta[o] - a*mean;
    }
}

// ---------------- kernel 5: affine + relu + transpose to (B,O,N) ----------------
__global__ void __launch_bounds__(256, 1) output_kernel(float* __restrict__ out){
    __shared__ float smx[64][65];
    __shared__ float smn[64][65];
    const int tid = threadIdx.x;
    const int b = blockIdx.x >> 6;
    const int nbase = (blockIdx.x & 63) * 64;
    const float4* hmaxf = reinterpret_cast<const float4*>(g_hmax);
    const float4* hminf = reinterpret_cast<const float4*>(g_hmin);

    #pragma unroll
    for (int it = 0; it < 4; ++it){
        int idx = it*256 + tid;
        int r = idx >> 4, cc = idx & 15;
        float4 v = __ldg(hmaxf + (b*NPTS + nbase + r)*16 + cc);
        smx[r][cc*4+0] = v.x; smx[r][cc*4+1] = v.y; smx[r][cc*4+2] = v.z; smx[r][cc*4+3] = v.w;
        float4 w = __ldg(hminf + (b*NPTS + nbase + r)*16 + cc);
        smn[r][cc*4+0] = w.x; smn[r][cc*4+1] = w.y; smn[r][cc*4+2] = w.z; smn[r][cc*4+3] = w.w;
    }
    __syncthreads();

    #pragma unroll
    for (int it = 0; it < 16; ++it){
        int o  = it*4 + (tid >> 6);
        int nn = tid & 63;
        float a = g_a[o], c = g_c[o];
        float h = (a >= 0.f) ? smx[nn][o] : smn[nn][o];
        out[b*NOUT*NPTS + o*NPTS + nbase + nn] = fmaxf(fmaf(a, h, c), 0.f);
    }
}

// ---------------- launch ----------------
extern "C" void kernel_launch(void* const* d_in, const int* in_sizes, int n_in,
                              void* d_out, int out_size){
    const float* points = (const float*)d_in[0];   // (B, C, N)
    const float* W      = (const float*)d_in[1];   // (O, 2C)
    const float* gamma  = (const float*)d_in[2];   // (O,)
    const float* beta   = (const float*)d_in[3];   // (O,)
    float* out = (float*)d_out;                    // (B, O, N)

    cudaFuncSetAttribute((const void*)knn_kernel,
                         cudaFuncAttributeMaxDynamicSharedMemorySize, KNN_SMEM);
    cudaFuncSetAttribute((const void*)ygemm_kernel,
                         cudaFuncAttributeMaxDynamicSharedMemorySize, 64*1024);

    wprep_kernel    <<<16, 256>>>(W);
    sqnorm_kernel   <<<64, 256>>>(points);
    zero_kernel     <<<1, 64>>>();
    prep_bf16_kernel<<<256, 256>>>(points);
    knn_kernel      <<<BATCH*(NPTS/128), 512, KNN_SMEM>>>();
    ygemm_kernel    <<<BATCH*(NPTS/128), 256, 64*1024>>>(points);
    gather_kernel   <<<BATCH*(NPTS/64), 256>>>();
    finalize_kernel <<<1, 64>>>(gamma, beta);
    output_kernel   <<<BATCH*(NPTS/64), 256>>>(out);
}

// round 9
// speedup vs baseline: 1.7933x; 1.7933x over previous
#include <cuda_runtime.h>
#include <cstdint>

#define BATCH 4
#define CH    64
#define NPTS  4096
#define KNN   32
#define NOUT  64
#define NCHUNK (NPTS/128)

// ---------------- device scratch (static: no allocations allowed) ----------------
__device__ float g_sq   [BATCH*NPTS];
__device__ int   g_idx  [BATCH*NPTS*KNN];
__device__ float g_Y1   [BATCH*NPTS*NOUT];
__device__ float g_Y2   [BATCH*NPTS*NOUT];
__device__ float g_hmax [BATCH*NPTS*NOUT];
__device__ float g_hmin [BATCH*NPTS*NOUT];
__device__ float g_Wt1  [CH*NOUT];
__device__ float g_Wt2  [CH*NOUT];
__device__ float g_sum  [NOUT];
__device__ float g_sumsq[NOUT];
__device__ float g_a    [NOUT];
__device__ float g_c    [NOUT];

// ---------------- packed fp32x2 helpers (Blackwell FFMA2) ----------------
__device__ __forceinline__ unsigned long long pack2(float x){
    unsigned long long d; unsigned int xi = __float_as_uint(x);
    asm("mov.b64 %0, {%1, %1};" : "=l"(d) : "r"(xi));
    return d;
}
__device__ __forceinline__ unsigned long long fma2(unsigned long long a,
                                                   unsigned long long b,
                                                   unsigned long long c){
    unsigned long long d;
    asm("fma.rn.f32x2 %0, %1, %2, %3;" : "=l"(d) : "l"(a), "l"(b), "l"(c));
    return d;
}
__device__ __forceinline__ float2 u2f2(unsigned long long u){
    float2 f;
    asm("mov.b64 {%0, %1}, %2;" : "=f"(f.x), "=f"(f.y) : "l"(u));
    return f;
}
__device__ __forceinline__ uint32_t smem_u32(const void* p){
    uint32_t a;
    asm("{ .reg .u64 t; cvta.to.shared.u64 t, %1; cvt.u32.u64 %0, t; }" : "=r"(a) : "l"(p));
    return a;
}
__device__ __forceinline__ void cp16(uint32_t dst, const void* src){
    asm volatile("cp.async.ca.shared.global [%0], [%1], 16;" :: "r"(dst), "l"(src));
}

// ---------------- kernel 0a: Wt1 = (W1-W2)^T, Wt2 = W2^T ----------------
__global__ void wprep_kernel(const float* __restrict__ W){
    int t = blockIdx.x*256 + threadIdx.x;
    if (t < CH*NOUT){
        int o = t & 63, c = t >> 6;
        float w1 = W[o*2*CH + c];
        float w2 = W[o*2*CH + CH + c];
        g_Wt1[c*NOUT + o] = w1 - w2;
        g_Wt2[c*NOUT + o] = w2;
    }
}

// ---------------- kernel 0b: squared norms ----------------
__global__ void sqnorm_kernel(const float* __restrict__ points){
    int t = blockIdx.x*256 + threadIdx.x;         // 0..16383
    int b = t >> 12, n = t & (NPTS-1);
    const float* P = points + b*CH*NPTS + n;
    float s = 0.f;
    #pragma unroll
    for (int c = 0; c < CH; ++c){ float v = __ldg(P + c*NPTS); s = fmaf(v, v, s); }
    g_sq[t] = s;
}

// ---------------- kernel 0c: zero BN accumulators (graph replays!) ----------------
__global__ void zero_kernel(){
    int t = threadIdx.x;
    if (t < NOUT){ g_sum[t] = 0.f; g_sumsq[t] = 0.f; }
}

// ---------------- kernel 1: fused distance GEMM + register top-32 ----------------
// grid = BATCH*64 blocks x 512 threads (16 warps), 2 blocks/SM (64 regs).
// Block owns 64 queries; warp w owns queries [4w, 4w+4). Streams 4096
// candidates in chunks of 128, double-buffered via cp.async; each lane scores
// 4 queries x 4 candidates. Qs pre-scaled by -2; acc init = sq_m, so
// score = sq_m - 2*dot accumulates directly. Per-(warp,query) top-32 kept as
// a sorted-ascending lane-per-rank list with ballot + shfl_up inserts.
// smem: Qs[64][64] 16K + Cs 2x[64][128] 64K + Ss[4096] 16K = 96KB.
__global__ void __launch_bounds__(512, 2) knn_kernel(const float* __restrict__ points){
    extern __shared__ float sm[];
    float* Qs = sm;               // [64][64]  (scaled by -2)
    float* Cs = Qs + 64*64;       // 2 x [64][128]
    float* Ss = Cs + 2*64*128;    // [4096] candidate sq-norms
    const uint32_t csb = smem_u32(Cs);

    const int tid  = threadIdx.x;
    const int lane = tid & 31;
    const int wid  = tid >> 5;
    const int b     = blockIdx.x >> 6;
    const int qbase = (blockIdx.x & 63) * 64;
    const float* P = points + b*CH*NPTS;

    // load query tile Qs[c][i], scaled by -2  (1024 float4 -> 2 each)
    #pragma unroll
    for (int it = 0; it < 2; ++it){
        int idx = it*512 + tid;
        int c = idx >> 4, i4 = idx & 15;
        float4 v = __ldg(reinterpret_cast<const float4*>(P + c*NPTS + qbase) + i4);
        v.x *= -2.f; v.y *= -2.f; v.z *= -2.f; v.w *= -2.f;
        reinterpret_cast<float4*>(Qs + c*64)[i4] = v;
    }
    // load sq-norm cache (1024 float4 -> 2 each)
    #pragma unroll
    for (int it = 0; it < 2; ++it){
        int idx = it*512 + tid;
        reinterpret_cast<float4*>(Ss)[idx] =
            __ldg(reinterpret_cast<const float4*>(g_sq + b*NPTS) + idx);
    }

    // prologue: async-fill chunk 0 into buffer 0
    #pragma unroll
    for (int it = 0; it < 4; ++it){
        int idx = it*512 + tid;
        int c = idx >> 5, i4 = idx & 31;
        cp16(csb + (uint32_t)((c*128 + i4*4)*4), P + c*NPTS + i4*4);
    }
    asm volatile("cp.async.commit_group;");

    // per-(warp,query) sorted list: lane l holds l-th smallest
    float Lv[4]; int Li[4]; float thr[4];
    #pragma unroll
    for (int qi = 0; qi < 4; ++qi){ Lv[qi] = 3.0e38f; Li[qi] = 0; thr[qi] = 3.0e38f; }

    const int q0 = wid * 4;      // this warp's first query (broadcast smem reads)
    const int m0 = lane * 4;     // this lane's candidate base within chunk

    #pragma unroll 1
    for (int chunk = 0; chunk < NCHUNK; ++chunk){
        const int mbase = chunk * 128;
        const float* Cb = Cs + (chunk & 1) * (64*128);

        // prefetch next chunk into the other buffer, then wait for current
        if (chunk + 1 < NCHUNK){
            const uint32_t dstb = csb + (uint32_t)(((chunk+1) & 1) * 64*128*4);
            const float* src = P + (chunk+1)*128;
            #pragma unroll
            for (int it = 0; it < 4; ++it){
                int idx = it*512 + tid;
                int c = idx >> 5, i4 = idx & 31;
                cp16(dstb + (uint32_t)((c*128 + i4*4)*4), src + c*NPTS + i4*4);
            }
            asm volatile("cp.async.commit_group;");
            asm volatile("cp.async.wait_group 1;");
        } else {
            asm volatile("cp.async.wait_group 0;");
        }
        __syncthreads();     // current buffer complete across all threads

        // acc init = sq of candidates
        float4 sqv = *reinterpret_cast<const float4*>(Ss + mbase + m0);
        unsigned long long acc[2][4];
        acc[0][0] = acc[1][0] = pack2(sqv.x);
        acc[0][1] = acc[1][1] = pack2(sqv.y);
        acc[0][2] = acc[1][2] = pack2(sqv.z);
        acc[0][3] = acc[1][3] = pack2(sqv.w);

        // GEMM: 4 queries (2 f32x2 pairs) x 4 candidates per lane
        #pragma unroll 4
        for (int c = 0; c < CH; ++c){
            ulonglong2 qv = *reinterpret_cast<const ulonglong2*>(Qs + c*64 + q0); // bcast
            float4 cv = *reinterpret_cast<const float4*>(Cb + c*128 + m0);
            unsigned long long bp0 = pack2(cv.x), bp1 = pack2(cv.y),
                               bp2 = pack2(cv.z), bp3 = pack2(cv.w);
            acc[0][0] = fma2(qv.x, bp0, acc[0][0]);
            acc[0][1] = fma2(qv.x, bp1, acc[0][1]);
            acc[0][2] = fma2(qv.x, bp2, acc[0][2]);
            acc[0][3] = fma2(qv.x, bp3, acc[0][3]);
            acc[1][0] = fma2(qv.y, bp0, acc[1][0]);
            acc[1][1] = fma2(qv.y, bp1, acc[1][1]);
            acc[1][2] = fma2(qv.y, bp2, acc[1][2]);
            acc[1][3] = fma2(qv.y, bp3, acc[1][3]);
        }

        // unpack scores: sc[qi][j]
        float sc[4][4];
        #pragma unroll
        for (int p = 0; p < 2; ++p){
            float2 d0 = u2f2(acc[p][0]), d1 = u2f2(acc[p][1]);
            float2 d2 = u2f2(acc[p][2]), d3 = u2f2(acc[p][3]);
            sc[2*p  ][0] = d0.x; sc[2*p  ][1] = d1.x; sc[2*p  ][2] = d2.x; sc[2*p  ][3] = d3.x;
            sc[2*p+1][0] = d0.y; sc[2*p+1][1] = d1.y; sc[2*p+1][2] = d2.y; sc[2*p+1][3] = d3.y;
        }

        // selection with per-query min-prefilter
        #pragma unroll
        for (int qi = 0; qi < 4; ++qi){
            float mn = fminf(fminf(sc[qi][0], sc[qi][1]), fminf(sc[qi][2], sc[qi][3]));
            if (!__any_sync(0xffffffffu, mn < thr[qi])) continue;
            #pragma unroll
            for (int j = 0; j < 4; ++j){
                float sj = sc[qi][j];
                unsigned mask = __ballot_sync(0xffffffffu, sj < thr[qi]);
                while (mask){
                    int src = __ffs(mask) - 1;
                    mask &= mask - 1;
                    float v = __shfl_sync(0xffffffffu, sj, src);
                    int gi = mbase + src*4 + j;
                    int pos = __popc(__ballot_sync(0xffffffffu, Lv[qi] <= v));
                    float upv = __shfl_up_sync(0xffffffffu, Lv[qi], 1);
                    int   upi = __shfl_up_sync(0xffffffffu, Li[qi], 1);
                    if (lane == pos){ Lv[qi] = v; Li[qi] = gi; }
                    else if (lane > pos){ Lv[qi] = upv; Li[qi] = upi; }
                    thr[qi] = __shfl_sync(0xffffffffu, Lv[qi], 31);
                    mask &= __ballot_sync(0xffffffffu, sj < thr[qi]);
                }
            }
        }
        __syncthreads();   // all warps done reading this buffer before its refill
    }

    // write indices: lane l holds l-th nearest of each owned query
    #pragma unroll
    for (int qi = 0; qi < 4; ++qi)
        g_idx[(b*NPTS + qbase + q0 + qi)*KNN + lane] = Li[qi];
}

// ---------------- kernel 2: Y1 = X*(W1-W2)^T, Y2 = X*W2^T ----------------
__global__ void __launch_bounds__(256, 1) ygemm_kernel(const float* __restrict__ points){
    extern __shared__ float smf[];
    float* Xs  = smf;           // [64][128]
    float* W1s = Xs + 64*128;   // [64][64]
    float* W2s = W1s + 64*64;   // [64][64]

    const int tid = threadIdx.x;
    const int b = blockIdx.x >> 5;
    const int nbase = (blockIdx.x & 31) * 128;
    const float* P = points + b*CH*NPTS;

    #pragma unroll
    for (int it = 0; it < 8; ++it){
        int idx = it*256 + tid;
        int c = idx >> 5, i4 = idx & 31;
        reinterpret_cast<float4*>(Xs + c*128)[i4] =
            __ldg(reinterpret_cast<const float4*>(P + c*NPTS + nbase) + i4);
    }
    #pragma unroll
    for (int it = 0; it < 4; ++it){
        int idx = it*256 + tid;
        reinterpret_cast<float4*>(W1s)[idx] = __ldg(reinterpret_cast<const float4*>(g_Wt1) + idx);
        reinterpret_cast<float4*>(W2s)[idx] = __ldg(reinterpret_cast<const float4*>(g_Wt2) + idx);
    }
    __syncthreads();

    const int n0 = (tid & 31) * 4;
    const int o0 = (tid >> 5) * 8;
    float acc1[4][8], acc2[4][8];
    #pragma unroll
    for (int j = 0; j < 4; ++j)
        #pragma unroll
        for (int r = 0; r < 8; ++r){ acc1[j][r] = 0.f; acc2[j][r] = 0.f; }

    #pragma unroll 8
    for (int c = 0; c < CH; ++c){
        float4 a   = *reinterpret_cast<const float4*>(Xs  + c*128 + n0);
        float4 w10 = *reinterpret_cast<const float4*>(W1s + c*64 + o0);
        float4 w11 = *reinterpret_cast<const float4*>(W1s + c*64 + o0 + 4);
        float4 w20 = *reinterpret_cast<const float4*>(W2s + c*64 + o0);
        float4 w21 = *reinterpret_cast<const float4*>(W2s + c*64 + o0 + 4);
        float af[4]  = {a.x, a.y, a.z, a.w};
        float w1f[8] = {w10.x,w10.y,w10.z,w10.w,w11.x,w11.y,w11.z,w11.w};
        float w2f[8] = {w20.x,w20.y,w20.z,w20.w,w21.x,w21.y,w21.z,w21.w};
        #pragma unroll
        for (int j = 0; j < 4; ++j)
            #pragma unroll
            for (int r = 0; r < 8; ++r){
                acc1[j][r] = fmaf(af[j], w1f[r], acc1[j][r]);
                acc2[j][r] = fmaf(af[j], w2f[r], acc2[j][r]);
            }
    }

    #pragma unroll
    for (int j = 0; j < 4; ++j){
        int row = (b*NPTS + nbase + n0 + j)*NOUT + o0;
        *reinterpret_cast<float4*>(g_Y1 + row)     = make_float4(acc1[j][0],acc1[j][1],acc1[j][2],acc1[j][3]);
        *reinterpret_cast<float4*>(g_Y1 + row + 4) = make_float4(acc1[j][4],acc1[j][5],acc1[j][6],acc1[j][7]);
        *reinterpret_cast<float4*>(g_Y2 + row)     = make_float4(acc2[j][0],acc2[j][1],acc2[j][2],acc2[j][3]);
        *reinterpret_cast<float4*>(g_Y2 + row + 4) = make_float4(acc2[j][4],acc2[j][5],acc2[j][6],acc2[j][7]);
    }
}

// ---------------- kernel 3: gather neighbors, h stats, per-(n,o) max/min over k ----------------
__global__ void __launch_bounds__(256, 1) gather_kernel(){
    __shared__ float ssum[NOUT], ssum2[NOUT];
    const int tid = threadIdx.x;
    if (tid < NOUT){ ssum[tid] = 0.f; ssum2[tid] = 0.f; }
    __syncthreads();

    const int b = blockIdx.x >> 6;
    const int nbase = (blockIdx.x & 63) * 64;
    const int lane = tid & 31, wid = tid >> 5;
    const int half = lane >> 4;
    const int c4 = lane & 15;

    const float4* Y1f = reinterpret_cast<const float4*>(g_Y1);
    const float4* Y2f = reinterpret_cast<const float4*>(g_Y2);
    float4* hmaxf = reinterpret_cast<float4*>(g_hmax);
    float4* hminf = reinterpret_cast<float4*>(g_hmin);

    float a0=0.f, a1=0.f, a2=0.f, a3=0.f;
    float b0=0.f, b1=0.f, b2=0.f, b3=0.f;

    #pragma unroll 1
    for (int it = 0; it < 4; ++it){
        int np  = nbase + it*16 + wid*2;
        int bnp = b*NPTS + np;
        int ia = g_idx[ bnp   *KNN + lane];
        int ib = g_idx[(bnp+1)*KNN + lane];
        int bn = bnp + half;
        float4 y1 = __ldg(Y1f + bn*16 + c4);
        float4 mx = make_float4(-3.0e38f,-3.0e38f,-3.0e38f,-3.0e38f);
        float4 mn = make_float4( 3.0e38f, 3.0e38f, 3.0e38f, 3.0e38f);
        #pragma unroll
        for (int k = 0; k < KNN; ++k){
            int ma = __shfl_sync(0xffffffffu, ia, k);
            int mb = __shfl_sync(0xffffffffu, ib, k);
            int m  = half ? mb : ma;
            float4 y2 = __ldg(Y2f + (b*NPTS + m)*16 + c4);
            float h0 = y1.x + y2.x, h1 = y1.y + y2.y, h2 = y1.z + y2.z, h3 = y1.w + y2.w;
            a0 += h0; a1 += h1; a2 += h2; a3 += h3;
            b0 = fmaf(h0,h0,b0); b1 = fmaf(h1,h1,b1); b2 = fmaf(h2,h2,b2); b3 = fmaf(h3,h3,b3);
            mx.x = fmaxf(mx.x,h0); mx.y = fmaxf(mx.y,h1); mx.z = fmaxf(mx.z,h2); mx.w = fmaxf(mx.w,h3);
            mn.x = fminf(mn.x,h0); mn.y = fminf(mn.y,h1); mn.z = fminf(mn.z,h2); mn.w = fminf(mn.w,h3);
        }
        hmaxf[bn*16 + c4] = mx;
        hminf[bn*16 + c4] = mn;
    }

    atomicAdd(&ssum [c4*4+0], a0); atomicAdd(&ssum [c4*4+1], a1);
    atomicAdd(&ssum [c4*4+2], a2); atomicAdd(&ssum [c4*4+3], a3);
    atomicAdd(&ssum2[c4*4+0], b0); atomicAdd(&ssum2[c4*4+1], b1);
    atomicAdd(&ssum2[c4*4+2], b2); atomicAdd(&ssum2[c4*4+3], b3);
    __syncthreads();
    if (tid < NOUT){
        atomicAdd(&g_sum[tid],   ssum[tid]);
        atomicAdd(&g_sumsq[tid], ssum2[tid]);
    }
}

// ---------------- kernel 4: BN scale/shift ----------------
__global__ void finalize_kernel(const float* __restrict__ gamma,
                                const float* __restrict__ beta){
    int o = threadIdx.x;
    if (o < NOUT){
        const float inv = 1.f / (float)(BATCH*NPTS*KNN);
        float mean = g_sum[o] * inv;
        float var  = g_sumsq[o] * inv - mean*mean;
        float a = gamma[o] * rsqrtf(var + 1e-5f);
        g_a[o] = a;
        g_c[o] = beta[o] - a*mean;
    }
}

// ---------------- kernel 5: affine + relu + transpose to (B,O,N) ----------------
__global__ void __launch_bounds__(256, 1) output_kernel(float* __restrict__ out){
    __shared__ float smx[64][65];
    __shared__ float smn[64][65];
    const int tid = threadIdx.x;
    const int b = blockIdx.x >> 6;
    const int nbase = (blockIdx.x & 63) * 64;
    const float4* hmaxf = reinterpret_cast<const float4*>(g_hmax);
    const float4* hminf = reinterpret_cast<const float4*>(g_hmin);

    #pragma unroll
    for (int it = 0; it < 4; ++it){
        int idx = it*256 + tid;
        int r = idx >> 4, cc = idx & 15;
        float4 v = __ldg(hmaxf + (b*NPTS + nbase + r)*16 + cc);
        smx[r][cc*4+0] = v.x; smx[r][cc*4+1] = v.y; smx[r][cc*4+2] = v.z; smx[r][cc*4+3] = v.w;
        float4 w = __ldg(hminf + (b*NPTS + nbase + r)*16 + cc);
        smn[r][cc*4+0] = w.x; smn[r][cc*4+1] = w.y; smn[r][cc*4+2] = w.z; smn[r][cc*4+3] = w.w;
    }
    __syncthreads();

    #pragma unroll
    for (int it = 0; it < 16; ++it){
        int o  = it*4 + (tid >> 6);
        int nn = tid & 63;
        float a = g_a[o], c = g_c[o];
        float h = (a >= 0.f) ? smx[nn][o] : smn[nn][o];
        out[b*NOUT*NPTS + o*NPTS + nbase + nn] = fmaxf(fmaf(a, h, c), 0.f);
    }
}

// ---------------- launch ----------------
extern "C" void kernel_launch(void* const* d_in, const int* in_sizes, int n_in,
                              void* d_out, int out_size){
    const float* points = (const float*)d_in[0];   // (B, C, N)
    const float* W      = (const float*)d_in[1];   // (O, 2C)
    const float* gamma  = (const float*)d_in[2];   // (O,)
    const float* beta   = (const float*)d_in[3];   // (O,)
    float* out = (float*)d_out;                    // (B, O, N)

    const int KNN_SMEM = (64*64 + 2*64*128 + 4096) * 4;   // 98304 B
    cudaFuncSetAttribute((const void*)knn_kernel,
                         cudaFuncAttributeMaxDynamicSharedMemorySize, KNN_SMEM);
    cudaFuncSetAttribute((const void*)ygemm_kernel,
                         cudaFuncAttributeMaxDynamicSharedMemorySize, 64*1024);

    wprep_kernel   <<<16, 256>>>(W);
    sqnorm_kernel  <<<64, 256>>>(points);
    zero_kernel    <<<1, 64>>>();
    knn_kernel     <<<BATCH*(NPTS/64), 512, KNN_SMEM>>>(points);
    ygemm_kernel   <<<BATCH*(NPTS/128), 256, 64*1024>>>(points);
    gather_kernel  <<<BATCH*(NPTS/64), 256>>>();
    finalize_kernel<<<1, 64>>>(gamma, beta);
    output_kernel  <<<BATCH*(NPTS/64), 256>>>(out);
}